// round 4
// baseline (speedup 1.0000x reference)
#include <cuda_runtime.h>
#include <math.h>

// Problem constants: N=200000, D=128, E=500000, NUM_REL=200, B=256
#define MAX_N    262144
#define MAX_REL  1024
#define MAX_B    4096

__device__ float g_p1[MAX_N];    // <node, W[0:D]>    (row term)
__device__ float g_p2[MAX_N];    // <node, W[D:2D]>   (col term)
__device__ float g_ph[MAX_N];    // <node, W[3D:4D]>  (head term)
__device__ float g_pr3[MAX_REL]; // <R, W[2D:3D]>     (rel term)
__device__ float g_pr5[MAX_REL]; // <R, W[4D:5D]>     (query term)
__device__ float g_hq[MAX_B];    // per-batch: head + query + bias

// ---------------------------------------------------------------------------
// Pass 1 (fused): node + relation projections. One warp per row.
// Rows [0,N): node rows -> p1/p2/ph.  Rows [N, N+NUM_REL): R rows -> pr3/pr5.
// D=128 = 32 lanes x float4 -> 512B coalesced per row.
// ---------------------------------------------------------------------------
__global__ void proj_kernel(const float4* __restrict__ ne,
                            const float4* __restrict__ Rm,
                            const float4* __restrict__ w,  // W as float4[160]
                            int N, int NUM_REL) {
    int lane = threadIdx.x & 31;
    int row  = (blockIdx.x * blockDim.x + threadIdx.x) >> 5;
    if (row >= N + NUM_REL) return;

    if (row < N) {
        float4 a  = ne[(size_t)row * 32 + lane];
        float4 w1 = __ldg(&w[lane]);        // W[0:128]
        float4 w2 = __ldg(&w[32 + lane]);   // W[128:256]
        float4 w3 = __ldg(&w[96 + lane]);   // W[384:512]
        float s1 = a.x*w1.x + a.y*w1.y + a.z*w1.z + a.w*w1.w;
        float s2 = a.x*w2.x + a.y*w2.y + a.z*w2.z + a.w*w2.w;
        float s3 = a.x*w3.x + a.y*w3.y + a.z*w3.z + a.w*w3.w;
        #pragma unroll
        for (int o = 16; o; o >>= 1) {
            s1 += __shfl_xor_sync(0xffffffffu, s1, o);
            s2 += __shfl_xor_sync(0xffffffffu, s2, o);
            s3 += __shfl_xor_sync(0xffffffffu, s3, o);
        }
        if (lane == 0) {
            g_p1[row] = s1;
            g_p2[row] = s2;
            g_ph[row] = s3;
        }
    } else {
        int rr = row - N;
        float4 a  = Rm[(size_t)rr * 32 + lane];
        float4 w3 = __ldg(&w[64 + lane]);    // W[256:384]
        float4 w5 = __ldg(&w[128 + lane]);   // W[512:640]
        float s3 = a.x*w3.x + a.y*w3.y + a.z*w3.z + a.w*w3.w;
        float s5 = a.x*w5.x + a.y*w5.y + a.z*w5.z + a.w*w5.w;
        #pragma unroll
        for (int o = 16; o; o >>= 1) {
            s3 += __shfl_xor_sync(0xffffffffu, s3, o);
            s5 += __shfl_xor_sync(0xffffffffu, s5, o);
        }
        if (lane == 0) {
            g_pr3[rr] = s3;
            g_pr5[rr] = s5;
        }
    }
}

// ---------------------------------------------------------------------------
// Pass 2: per-batch head+query scalar (B=256) -> 1KB L1-hot table for pass 3.
// ---------------------------------------------------------------------------
__global__ void batch_combine_kernel(const int* __restrict__ h_index,
                                     const int* __restrict__ r_index,
                                     const float* __restrict__ bvec,
                                     int B) {
    int i = blockIdx.x * blockDim.x + threadIdx.x;
    if (i >= B) return;
    g_hq[i] = g_ph[h_index[i]] + g_pr5[r_index[i]] + bvec[0];
}

// ---------------------------------------------------------------------------
// Pass 3: per-edge gate, 4 edges/thread. 5 coalesced 16B loads then 16
// independent gathers in flight (p1/p2 tables ~800KB: L2-resident;
// pr3/hq: L1-hot). Fast-math logit+sigmoid.
// ---------------------------------------------------------------------------
__device__ __forceinline__ float gate_one(int r, int c, int t, int bb, float u) {
    float s = g_p1[r] + g_p2[c] + g_pr3[t] + g_hq[bb];
    // eps = (2*BIAS-1)*u + (1-BIAS), BIAS=1e-4
    float eps = fmaf(-0.9998f, u, 0.9999f);
    // logit(eps) = log(eps/(1-eps)); gate = (logit + s)/TEMP, TEMP=5
    float logit = __logf(__fdividef(eps, 1.0f - eps));
    float g = (logit + s) * 0.2f;
    return __fdividef(1.0f, 1.0f + __expf(-g));
}

__global__ void edge_gate_kernel(const int4* __restrict__ rows4,
                                 const int4* __restrict__ cols4,
                                 const int4* __restrict__ type4,
                                 const int4* __restrict__ batch4,
                                 const float4* __restrict__ eps4,
                                 float4* __restrict__ out4,
                                 int ngroups) {
    int i = blockIdx.x * blockDim.x + threadIdx.x;
    if (i >= ngroups) return;

    int4   r  = rows4[i];
    int4   c  = cols4[i];
    int4   t  = type4[i];
    int4   bb = batch4[i];
    float4 u  = eps4[i];

    float4 o;
    o.x = gate_one(r.x, c.x, t.x, bb.x, u.x);
    o.y = gate_one(r.y, c.y, t.y, bb.y, u.y);
    o.z = gate_one(r.z, c.z, t.z, bb.z, u.z);
    o.w = gate_one(r.w, c.w, t.w, bb.w, u.w);
    out4[i] = o;
}

// Scalar fallback for E not divisible by 4 (not hit for E=500000).
__global__ void edge_gate_tail_kernel(const int* __restrict__ rows,
                                      const int* __restrict__ cols,
                                      const int* __restrict__ edge_type,
                                      const int* __restrict__ batch_id,
                                      const float* __restrict__ eps_u,
                                      float* __restrict__ out,
                                      int start, int E) {
    int e = start + blockIdx.x * blockDim.x + threadIdx.x;
    if (e >= E) return;
    out[e] = gate_one(rows[e], cols[e], edge_type[e], batch_id[e], eps_u[e]);
}

extern "C" void kernel_launch(void* const* d_in, const int* in_sizes, int n_in,
                              void* d_out, int out_size) {
    const float* node_embeds = (const float*)d_in[0];  // (N, 128)
    const float* R           = (const float*)d_in[1];  // (NUM_REL, 128)
    const float* W           = (const float*)d_in[2];  // (640, 1)
    const float* b           = (const float*)d_in[3];  // (1,)
    const float* eps_u       = (const float*)d_in[4];  // (E, 1)
    const int*   edge_index  = (const int*)d_in[5];    // (2, E) int32
    const int*   edge_type   = (const int*)d_in[6];    // (E,)
    const int*   batch_id    = (const int*)d_in[7];    // (E,)
    const int*   h_index     = (const int*)d_in[8];    // (B,)
    const int*   r_index     = (const int*)d_in[9];    // (B,)
    float* out = (float*)d_out;

    const int D = 128;
    int N       = in_sizes[0] / D;
    int NUM_REL = in_sizes[1] / D;
    int E       = in_sizes[4];
    int B       = in_sizes[8];

    // Pass 1: fused projections, 1 row per warp.
    {
        int total_rows = N + NUM_REL;
        int threads = 256;
        int warps_per_block = threads / 32;
        int blocks = (total_rows + warps_per_block - 1) / warps_per_block;
        proj_kernel<<<blocks, threads>>>((const float4*)node_embeds,
                                         (const float4*)R,
                                         (const float4*)W, N, NUM_REL);
    }
    // Pass 2: per-batch combine.
    {
        int threads = 256;
        int blocks = (B + threads - 1) / threads;
        batch_combine_kernel<<<blocks, threads>>>(h_index, r_index, b, B);
    }
    // Pass 3: edge gate, 4 edges/thread. The cols slice starts at byte
    // offset 4*E from rows; 16B-aligned when E % 4 == 0 (tail handles rest).
    {
        int ngroups = E >> 2;
        int threads = 256;
        int blocks = (ngroups + threads - 1) / threads;
        if (blocks > 0)
            edge_gate_kernel<<<blocks, threads>>>((const int4*)edge_index,
                                                  (const int4*)(edge_index + E),
                                                  (const int4*)edge_type,
                                                  (const int4*)batch_id,
                                                  (const float4*)eps_u,
                                                  (float4*)out, ngroups);
        int tail_start = ngroups << 2;
        if (E - tail_start > 0) {
            edge_gate_tail_kernel<<<1, 256>>>(edge_index, edge_index + E,
                                              edge_type, batch_id, eps_u, out,
                                              tail_start, E);
        }
    }
}

// round 6
// speedup vs baseline: 1.2936x; 1.2936x over previous
#include <cuda_runtime.h>
#include <math.h>

// Problem constants: N=200000, D=128, E=500000, NUM_REL=200, B=256
#define MAX_N    262144
#define MAX_REL  1024
#define MAX_B    4096

__device__ float g_p1[MAX_N];    // <node, W[0:D]>   (row term)
__device__ float g_p2[MAX_N];    // <node, W[D:2D]>  (col term)
__device__ float g_pr3[MAX_REL]; // <R, W[2D:3D]>    (rel term)
__device__ float g_hq[MAX_B];    // per-batch: head + query + bias

__device__ __forceinline__ float dot4(float4 a, float4 b) {
    return fmaf(a.x, b.x, fmaf(a.y, b.y, fmaf(a.z, b.z, a.w * b.w)));
}

__device__ __forceinline__ float warp_reduce(float v) {
    #pragma unroll
    for (int o = 16; o; o >>= 1) v += __shfl_xor_sync(0xffffffffu, v, o);
    return v;
}

// Reduce two warp-spread values with 6 shuffles instead of 10.
// Returns: lane 0 holds sum(s1), lane 16 holds sum(s2) (as the same reg).
__device__ __forceinline__ float pair_reduce(float s1, float s2, int lane) {
    s1 += __shfl_xor_sync(0xffffffffu, s1, 16);
    s2 += __shfl_xor_sync(0xffffffffu, s2, 16);
    float v = (lane < 16) ? s1 : s2;   // lanes 0-15: s1 partials, 16-31: s2
    v += __shfl_xor_sync(0xffffffffu, v, 8);
    v += __shfl_xor_sync(0xffffffffu, v, 4);
    v += __shfl_xor_sync(0xffffffffu, v, 2);
    v += __shfl_xor_sync(0xffffffffu, v, 1);
    return v;
}

// ---------------------------------------------------------------------------
// Pass 1: node projections. One warp per row, persistent grid-stride,
// 2 rows per iteration (8 x 128B loads in flight), pair-packed reductions.
// Rel rows appended after node rows.
// ---------------------------------------------------------------------------
__global__ void proj_kernel(const float4* __restrict__ ne,
                            const float4* __restrict__ Rm,
                            const float4* __restrict__ w,  // W as float4[160]
                            int N, int NUM_REL) {
    int lane   = threadIdx.x & 31;
    int warp0  = (blockIdx.x * blockDim.x + threadIdx.x) >> 5;
    int nwarps = (gridDim.x * blockDim.x) >> 5;

    float4 w1 = __ldg(&w[lane]);        // W[0:128]
    float4 w2 = __ldg(&w[32 + lane]);   // W[128:256]

    // Node rows, two at a time per warp.
    for (int rowA = warp0; rowA < N; rowA += 2 * nwarps) {
        int rowB = rowA + nwarps;
        float4 a = ne[(size_t)rowA * 32 + lane];
        bool hasB = rowB < N;
        float4 c;
        if (hasB) c = ne[(size_t)rowB * 32 + lane];

        float vA = pair_reduce(dot4(a, w1), dot4(a, w2), lane);
        if (lane == 0)  g_p1[rowA] = vA;
        if (lane == 16) g_p2[rowA] = vA;

        if (hasB) {
            float vB = pair_reduce(dot4(c, w1), dot4(c, w2), lane);
            if (lane == 0)  g_p1[rowB] = vB;
            if (lane == 16) g_p2[rowB] = vB;
        }
    }

    // Relation rows (200 total) — first 200 warps handle them.
    if (warp0 < NUM_REL) {
        float4 a  = Rm[(size_t)warp0 * 32 + lane];
        float4 w3 = __ldg(&w[64 + lane]);   // W[256:384]
        float s3 = warp_reduce(dot4(a, w3));
        if (lane == 0) g_pr3[warp0] = s3;
    }
}

// ---------------------------------------------------------------------------
// Pass 2: per-batch head+query dot (B=256, one warp each).
// ---------------------------------------------------------------------------
__global__ void batch_kernel(const float4* __restrict__ ne,
                             const float4* __restrict__ Rm,
                             const float4* __restrict__ w,
                             const int* __restrict__ h_index,
                             const int* __restrict__ r_index,
                             const float* __restrict__ bvec,
                             int B) {
    int lane = threadIdx.x & 31;
    int b = (blockIdx.x * blockDim.x + threadIdx.x) >> 5;
    if (b >= B) return;

    int h = __ldg(&h_index[b]);
    int r = __ldg(&r_index[b]);
    float4 a  = ne[(size_t)h * 32 + lane];
    float4 q  = Rm[(size_t)r * 32 + lane];
    float4 w4 = __ldg(&w[96 + lane]);    // W[384:512]  (head slot)
    float4 w5 = __ldg(&w[128 + lane]);   // W[512:640]  (query slot)

    float s = warp_reduce(dot4(a, w4) + dot4(q, w5));
    if (lane == 0) g_hq[b] = s + __ldg(&bvec[0]);
}

// ---------------------------------------------------------------------------
// Pass 3: per-edge gate, 4 edges/thread. 5 coalesced 16B loads then 16
// independent gathers in flight (p1/p2 ~800KB: L2-resident; pr3/hq: L1-hot).
// Fast-math logit+sigmoid.
// ---------------------------------------------------------------------------
__device__ __forceinline__ float gate_one(int r, int c, int t, int bb, float u) {
    float s = g_p1[r] + g_p2[c] + g_pr3[t] + g_hq[bb];
    // eps = (2*BIAS-1)*u + (1-BIAS), BIAS=1e-4
    float eps = fmaf(-0.9998f, u, 0.9999f);
    // logit(eps) = log(eps/(1-eps)); gate = (logit + s)/TEMP, TEMP=5
    float logit = __logf(__fdividef(eps, 1.0f - eps));
    float g = (logit + s) * 0.2f;
    return __fdividef(1.0f, 1.0f + __expf(-g));
}

__global__ void edge_gate_kernel(const int4* __restrict__ rows4,
                                 const int4* __restrict__ cols4,
                                 const int4* __restrict__ type4,
                                 const int4* __restrict__ batch4,
                                 const float4* __restrict__ eps4,
                                 float4* __restrict__ out4,
                                 int ngroups) {
    int i = blockIdx.x * blockDim.x + threadIdx.x;
    if (i >= ngroups) return;

    int4   r  = rows4[i];
    int4   c  = cols4[i];
    int4   t  = type4[i];
    int4   bb = batch4[i];
    float4 u  = eps4[i];

    float4 o;
    o.x = gate_one(r.x, c.x, t.x, bb.x, u.x);
    o.y = gate_one(r.y, c.y, t.y, bb.y, u.y);
    o.z = gate_one(r.z, c.z, t.z, bb.z, u.z);
    o.w = gate_one(r.w, c.w, t.w, bb.w, u.w);
    out4[i] = o;
}

// Scalar fallback for E not divisible by 4 (not hit for E=500000).
__global__ void edge_gate_tail_kernel(const int* __restrict__ rows,
                                      const int* __restrict__ cols,
                                      const int* __restrict__ edge_type,
                                      const int* __restrict__ batch_id,
                                      const float* __restrict__ eps_u,
                                      float* __restrict__ out,
                                      int start, int E) {
    int e = start + blockIdx.x * blockDim.x + threadIdx.x;
    if (e >= E) return;
    out[e] = gate_one(rows[e], cols[e], edge_type[e], batch_id[e], eps_u[e]);
}

extern "C" void kernel_launch(void* const* d_in, const int* in_sizes, int n_in,
                              void* d_out, int out_size) {
    const float* node_embeds = (const float*)d_in[0];  // (N, 128)
    const float* R           = (const float*)d_in[1];  // (NUM_REL, 128)
    const float* W           = (const float*)d_in[2];  // (640, 1)
    const float* b           = (const float*)d_in[3];  // (1,)
    const float* eps_u       = (const float*)d_in[4];  // (E, 1)
    const int*   edge_index  = (const int*)d_in[5];    // (2, E) int32
    const int*   edge_type   = (const int*)d_in[6];    // (E,)
    const int*   batch_id    = (const int*)d_in[7];    // (E,)
    const int*   h_index     = (const int*)d_in[8];    // (B,)
    const int*   r_index     = (const int*)d_in[9];    // (B,)
    float* out = (float*)d_out;

    const int D = 128;
    int N       = in_sizes[0] / D;
    int NUM_REL = in_sizes[1] / D;
    int E       = in_sizes[4];
    int B       = in_sizes[8];

    const float4* ne4 = (const float4*)node_embeds;
    const float4* R4  = (const float4*)R;
    const float4* W4  = (const float4*)W;

    // Pass 1: projections. Persistent grid-stride warps, 2 rows/iter.
    {
        int threads = 256;
        int blocks = 2048;   // 16384 warps -> ~12 node rows each (6 pair iters)
        int total_rows = N + NUM_REL;
        int max_blocks = (total_rows + 7) / 8;
        if (blocks > max_blocks) blocks = max_blocks;
        proj_kernel<<<blocks, threads>>>(ne4, R4, W4, N, NUM_REL);
    }
    // Pass 2: per-batch head+query dots (one warp per batch element).
    {
        int threads = 256;
        int blocks = (B * 32 + threads - 1) / threads;
        batch_kernel<<<blocks, threads>>>(ne4, R4, W4, h_index, r_index, b, B);
    }
    // Pass 3: edge gate, 4 edges/thread (cols slice 16B-aligned for E%4==0;
    // tail kernel covers any remainder).
    {
        int ngroups = E >> 2;
        int threads = 256;
        int blocks = (ngroups + threads - 1) / threads;
        if (blocks > 0)
            edge_gate_kernel<<<blocks, threads>>>((const int4*)edge_index,
                                                  (const int4*)(edge_index + E),
                                                  (const int4*)edge_type,
                                                  (const int4*)batch_id,
                                                  (const float4*)eps_u,
                                                  (float4*)out, ngroups);
        int tail_start = ngroups << 2;
        if (E - tail_start > 0) {
            edge_gate_tail_kernel<<<1, 256>>>(edge_index, edge_index + E,
                                              edge_type, batch_id, eps_u, out,
                                              tail_start, E);
        }
    }
}

// round 7
// speedup vs baseline: 1.3320x; 1.0297x over previous
#include <cuda_runtime.h>
#include <math.h>

// Problem constants: N=200000, D=128, E=500000, NUM_REL=200, B=256
#define MAX_N    262144
#define MAX_REL  1024
#define MAX_B    4096

__device__ float g_p1[MAX_N];    // <node, W[0:D]>   (row term)
__device__ float g_p2[MAX_N];    // <node, W[D:2D]>  (col term)
__device__ float g_pr3[MAX_REL]; // <R, W[2D:3D]>    (rel term)
__device__ float g_hq[MAX_B];    // per-batch: head + query + bias

__device__ __forceinline__ float dot4(float4 a, float4 b) {
    return fmaf(a.x, b.x, fmaf(a.y, b.y, fmaf(a.z, b.z, a.w * b.w)));
}

__device__ __forceinline__ float warp_reduce(float v) {
    #pragma unroll
    for (int o = 16; o; o >>= 1) v += __shfl_xor_sync(0xffffffffu, v, o);
    return v;
}

// Reduce two warp-spread values with 6 shuffles instead of 10.
// Result: lane 0 holds sum(s1), lane 16 holds sum(s2).
__device__ __forceinline__ float pair_reduce(float s1, float s2, int lane) {
    s1 += __shfl_xor_sync(0xffffffffu, s1, 16);
    s2 += __shfl_xor_sync(0xffffffffu, s2, 16);
    float v = (lane < 16) ? s1 : s2;
    v += __shfl_xor_sync(0xffffffffu, v, 8);
    v += __shfl_xor_sync(0xffffffffu, v, 4);
    v += __shfl_xor_sync(0xffffffffu, v, 2);
    v += __shfl_xor_sync(0xffffffffu, v, 1);
    return v;
}

__device__ __forceinline__ float4 ldcs4(const float4* p) {
    return __ldcs(p);   // streaming: evict-first, keep L2 for the gather tables
}

// ---------------------------------------------------------------------------
// Pass 1 (fused): node projections + relation projections + per-batch dots.
// One warp per row, persistent grid-stride, 4 rows per iteration
// (16 x 128B wavefronts in flight), pair-packed reductions.
// ---------------------------------------------------------------------------
__global__ void proj_kernel(const float4* __restrict__ ne,
                            const float4* __restrict__ Rm,
                            const float4* __restrict__ w,  // W as float4[160]
                            const int* __restrict__ h_index,
                            const int* __restrict__ r_index,
                            const float* __restrict__ bvec,
                            int N, int NUM_REL, int B) {
    int lane   = threadIdx.x & 31;
    int warp0  = (blockIdx.x * blockDim.x + threadIdx.x) >> 5;
    int nwarps = (gridDim.x * blockDim.x) >> 5;

    float4 w1 = __ldg(&w[lane]);        // W[0:128]
    float4 w2 = __ldg(&w[32 + lane]);   // W[128:256]

    // Node rows, four at a time per warp (max MLP before dependent math).
    for (int r0 = warp0; r0 < N; r0 += 4 * nwarps) {
        int r1 = r0 + nwarps, r2 = r0 + 2 * nwarps, r3 = r0 + 3 * nwarps;
        float4 a0 = ldcs4(&ne[(size_t)r0 * 32 + lane]);
        float4 a1, a2, a3;
        bool h1 = r1 < N, h2 = r2 < N, h3 = r3 < N;
        if (h1) a1 = ldcs4(&ne[(size_t)r1 * 32 + lane]);
        if (h2) a2 = ldcs4(&ne[(size_t)r2 * 32 + lane]);
        if (h3) a3 = ldcs4(&ne[(size_t)r3 * 32 + lane]);

        float v0 = pair_reduce(dot4(a0, w1), dot4(a0, w2), lane);
        if (lane == 0)  g_p1[r0] = v0;
        if (lane == 16) g_p2[r0] = v0;
        if (h1) {
            float v1 = pair_reduce(dot4(a1, w1), dot4(a1, w2), lane);
            if (lane == 0)  g_p1[r1] = v1;
            if (lane == 16) g_p2[r1] = v1;
        }
        if (h2) {
            float v2 = pair_reduce(dot4(a2, w1), dot4(a2, w2), lane);
            if (lane == 0)  g_p1[r2] = v2;
            if (lane == 16) g_p2[r2] = v2;
        }
        if (h3) {
            float v3 = pair_reduce(dot4(a3, w1), dot4(a3, w2), lane);
            if (lane == 0)  g_p1[r3] = v3;
            if (lane == 16) g_p2[r3] = v3;
        }
    }

    // Relation rows (NUM_REL=200): first NUM_REL warps.
    if (warp0 < NUM_REL) {
        float4 a  = __ldg(&Rm[(size_t)warp0 * 32 + lane]);
        float4 w3 = __ldg(&w[64 + lane]);   // W[256:384]
        float s3 = warp_reduce(dot4(a, w3));
        if (lane == 0) g_pr3[warp0] = s3;
    }

    // Per-batch head+query dots (B=256): next B warps (disjoint warp range
    // not required — independent work, any warp can do it).
    int bw = warp0 - NUM_REL;
    if (bw >= 0 && bw < B) {
        int h = __ldg(&h_index[bw]);
        int r = __ldg(&r_index[bw]);
        float4 a  = __ldg(&ne[(size_t)h * 32 + lane]);
        float4 q  = __ldg(&Rm[(size_t)r * 32 + lane]);
        float4 w4 = __ldg(&w[96 + lane]);    // W[384:512]  (head slot)
        float4 w5 = __ldg(&w[128 + lane]);   // W[512:640]  (query slot)
        float s = warp_reduce(dot4(a, w4) + dot4(q, w5));
        if (lane == 0) g_hq[bw] = s + __ldg(&bvec[0]);
    }
}

// ---------------------------------------------------------------------------
// Pass 2: per-edge gate, 4 edges/thread. 5 coalesced 16B loads then 16
// independent gathers in flight (p1/p2 ~800KB: L2-resident; pr3/hq: L1-hot).
// Fast-math logit+sigmoid.
// ---------------------------------------------------------------------------
__device__ __forceinline__ float gate_one(int r, int c, int t, int bb, float u) {
    float s = g_p1[r] + g_p2[c] + g_pr3[t] + g_hq[bb];
    // eps = (2*BIAS-1)*u + (1-BIAS), BIAS=1e-4
    float eps = fmaf(-0.9998f, u, 0.9999f);
    // logit(eps) = log(eps/(1-eps)); gate = (logit + s)/TEMP, TEMP=5
    float logit = __logf(__fdividef(eps, 1.0f - eps));
    float g = (logit + s) * 0.2f;
    return __fdividef(1.0f, 1.0f + __expf(-g));
}

__global__ void edge_gate_kernel(const int4* __restrict__ rows4,
                                 const int4* __restrict__ cols4,
                                 const int4* __restrict__ type4,
                                 const int4* __restrict__ batch4,
                                 const float4* __restrict__ eps4,
                                 float4* __restrict__ out4,
                                 int ngroups) {
    int i = blockIdx.x * blockDim.x + threadIdx.x;
    if (i >= ngroups) return;

    int4   r  = __ldcs(&rows4[i]);
    int4   c  = __ldcs(&cols4[i]);
    int4   t  = __ldcs(&type4[i]);
    int4   bb = __ldcs(&batch4[i]);
    float4 u  = __ldcs(&eps4[i]);

    float4 o;
    o.x = gate_one(r.x, c.x, t.x, bb.x, u.x);
    o.y = gate_one(r.y, c.y, t.y, bb.y, u.y);
    o.z = gate_one(r.z, c.z, t.z, bb.z, u.z);
    o.w = gate_one(r.w, c.w, t.w, bb.w, u.w);
    out4[i] = o;
}

// Scalar fallback for E not divisible by 4 (not hit for E=500000).
__global__ void edge_gate_tail_kernel(const int* __restrict__ rows,
                                      const int* __restrict__ cols,
                                      const int* __restrict__ edge_type,
                                      const int* __restrict__ batch_id,
                                      const float* __restrict__ eps_u,
                                      float* __restrict__ out,
                                      int start, int E) {
    int e = start + blockIdx.x * blockDim.x + threadIdx.x;
    if (e >= E) return;
    out[e] = gate_one(rows[e], cols[e], edge_type[e], batch_id[e], eps_u[e]);
}

extern "C" void kernel_launch(void* const* d_in, const int* in_sizes, int n_in,
                              void* d_out, int out_size) {
    const float* node_embeds = (const float*)d_in[0];  // (N, 128)
    const float* R           = (const float*)d_in[1];  // (NUM_REL, 128)
    const float* W           = (const float*)d_in[2];  // (640, 1)
    const float* b           = (const float*)d_in[3];  // (1,)
    const float* eps_u       = (const float*)d_in[4];  // (E, 1)
    const int*   edge_index  = (const int*)d_in[5];    // (2, E) int32
    const int*   edge_type   = (const int*)d_in[6];    // (E,)
    const int*   batch_id    = (const int*)d_in[7];    // (E,)
    const int*   h_index     = (const int*)d_in[8];    // (B,)
    const int*   r_index     = (const int*)d_in[9];    // (B,)
    float* out = (float*)d_out;

    const int D = 128;
    int N       = in_sizes[0] / D;
    int NUM_REL = in_sizes[1] / D;
    int E       = in_sizes[4];
    int B       = in_sizes[8];

    const float4* ne4 = (const float4*)node_embeds;
    const float4* R4  = (const float4*)R;
    const float4* W4  = (const float4*)W;

    // Pass 1: fused projections + batch dots. 2048 blocks x 8 warps.
    {
        int threads = 256;
        int blocks = 2048;   // 16384 warps -> ~12 node rows each (3 quad iters)
        proj_kernel<<<blocks, threads>>>(ne4, R4, W4, h_index, r_index, b,
                                         N, NUM_REL, B);
    }
    // Pass 2: edge gate, 4 edges/thread (cols slice 16B-aligned for E%4==0;
    // tail kernel covers any remainder).
    {
        int ngroups = E >> 2;
        int threads = 256;
        int blocks = (ngroups + threads - 1) / threads;
        if (blocks > 0)
            edge_gate_kernel<<<blocks, threads>>>((const int4*)edge_index,
                                                  (const int4*)(edge_index + E),
                                                  (const int4*)edge_type,
                                                  (const int4*)batch_id,
                                                  (const float4*)eps_u,
                                                  (float4*)out, ngroups);
        int tail_start = ngroups << 2;
        if (E - tail_start > 0) {
            edge_gate_tail_kernel<<<1, 256>>>(edge_index, edge_index + E,
                                              edge_type, batch_id, eps_u, out,
                                              tail_start, E);
        }
    }
}

// round 8
// speedup vs baseline: 1.5000x; 1.1261x over previous
#include <cuda_runtime.h>
#include <math.h>

// Problem constants: N=200000, D=128, E=500000, NUM_REL=200, B=256
#define MAX_N    262144
#define MAX_REL  1024
#define MAX_B    4096

__device__ float g_p1[MAX_N];    // <node, W[0:D]>   (row term)
__device__ float g_p2[MAX_N];    // <node, W[D:2D]>  (col term)
__device__ float g_pr3[MAX_REL]; // <R, W[2D:3D]>    (rel term)
__device__ float g_hq[MAX_B];    // per-batch: head + query + bias

__device__ __forceinline__ float dot4(float4 a, float4 b) {
    return fmaf(a.x, b.x, fmaf(a.y, b.y, fmaf(a.z, b.z, a.w * b.w)));
}

__device__ __forceinline__ float warp_reduce(float v) {
    #pragma unroll
    for (int o = 16; o; o >>= 1) v += __shfl_xor_sync(0xffffffffu, v, o);
    return v;
}

// Reduce two warp-spread values with 6 shuffles instead of 10.
// Result: lane 0 holds sum(s1), lane 16 holds sum(s2).
__device__ __forceinline__ float pair_reduce(float s1, float s2, int lane) {
    s1 += __shfl_xor_sync(0xffffffffu, s1, 16);
    s2 += __shfl_xor_sync(0xffffffffu, s2, 16);
    float v = (lane < 16) ? s1 : s2;
    v += __shfl_xor_sync(0xffffffffu, v, 8);
    v += __shfl_xor_sync(0xffffffffu, v, 4);
    v += __shfl_xor_sync(0xffffffffu, v, 2);
    v += __shfl_xor_sync(0xffffffffu, v, 1);
    return v;
}

// Single predicated store: lane 0 -> g_p1[row], lane 16 -> g_p2[row].
__device__ __forceinline__ void store_pair(int row, float v, int lane) {
    if ((lane & 15) == 0) {
        float* dst = (lane == 0) ? &g_p1[row] : &g_p2[row];
        *dst = v;
    }
}

__device__ __forceinline__ float4 ldcs4(const float4* p) {
    return __ldcs(p);   // streaming: evict-first, keep L2 for the gather tables
}

// ---------------------------------------------------------------------------
// Pass 1 (fused): node projections + relation projections + per-batch dots.
// One warp per row, persistent grid-stride, 4 rows per iteration
// (16 x 128B wavefronts in flight), pair-packed reductions.
// ---------------------------------------------------------------------------
__global__ void proj_kernel(const float4* __restrict__ ne,
                            const float4* __restrict__ Rm,
                            const float4* __restrict__ w,  // W as float4[160]
                            const int* __restrict__ h_index,
                            const int* __restrict__ r_index,
                            const float* __restrict__ bvec,
                            int N, int NUM_REL, int B) {
    int lane   = threadIdx.x & 31;
    int warp0  = (blockIdx.x * blockDim.x + threadIdx.x) >> 5;
    int nwarps = (gridDim.x * blockDim.x) >> 5;

    float4 w1 = __ldg(&w[lane]);        // W[0:128]
    float4 w2 = __ldg(&w[32 + lane]);   // W[128:256]

    // Node rows, four at a time per warp (max MLP before dependent math).
    for (int r0 = warp0; r0 < N; r0 += 4 * nwarps) {
        int r1 = r0 + nwarps, r2 = r0 + 2 * nwarps, r3 = r0 + 3 * nwarps;
        float4 a0 = ldcs4(&ne[(size_t)r0 * 32 + lane]);
        float4 a1, a2, a3;
        bool h1 = r1 < N, h2 = r2 < N, h3 = r3 < N;
        if (h1) a1 = ldcs4(&ne[(size_t)r1 * 32 + lane]);
        if (h2) a2 = ldcs4(&ne[(size_t)r2 * 32 + lane]);
        if (h3) a3 = ldcs4(&ne[(size_t)r3 * 32 + lane]);

        float v0 = pair_reduce(dot4(a0, w1), dot4(a0, w2), lane);
        store_pair(r0, v0, lane);
        if (h1) { float v1 = pair_reduce(dot4(a1, w1), dot4(a1, w2), lane); store_pair(r1, v1, lane); }
        if (h2) { float v2 = pair_reduce(dot4(a2, w1), dot4(a2, w2), lane); store_pair(r2, v2, lane); }
        if (h3) { float v3 = pair_reduce(dot4(a3, w1), dot4(a3, w2), lane); store_pair(r3, v3, lane); }
    }

    // Relation rows (NUM_REL=200): first NUM_REL warps.
    if (warp0 < NUM_REL) {
        float4 a  = __ldg(&Rm[(size_t)warp0 * 32 + lane]);
        float4 w3 = __ldg(&w[64 + lane]);   // W[256:384]
        float s3 = warp_reduce(dot4(a, w3));
        if (lane == 0) g_pr3[warp0] = s3;
    }

    // Per-batch head+query dots (B=256): warps [NUM_REL, NUM_REL+B).
    int bw = warp0 - NUM_REL;
    if (bw >= 0 && bw < B) {
        int h = __ldg(&h_index[bw]);
        int r = __ldg(&r_index[bw]);
        float4 a  = __ldg(&ne[(size_t)h * 32 + lane]);
        float4 q  = __ldg(&Rm[(size_t)r * 32 + lane]);
        float4 w4 = __ldg(&w[96 + lane]);    // W[384:512]  (head slot)
        float4 w5 = __ldg(&w[128 + lane]);   // W[512:640]  (query slot)
        float s = warp_reduce(dot4(a, w4) + dot4(q, w5));
        if (lane == 0) g_hq[bw] = s + __ldg(&bvec[0]);
    }
}

// ---------------------------------------------------------------------------
// Pass 2: per-edge gate, 2 edges/thread. High occupancy (977 blocks) with
// 8 independent gathers in flight per thread (p1/p2 ~800KB: L2-resident;
// pr3/hq: L1-hot). Fast-math logit+sigmoid.
// ---------------------------------------------------------------------------
__device__ __forceinline__ float gate_one(int r, int c, int t, int bb, float u) {
    float s = g_p1[r] + g_p2[c] + g_pr3[t] + g_hq[bb];
    // eps = (2*BIAS-1)*u + (1-BIAS), BIAS=1e-4
    float eps = fmaf(-0.9998f, u, 0.9999f);
    // logit(eps) = log(eps/(1-eps)); gate = (logit + s)/TEMP, TEMP=5
    float logit = __logf(__fdividef(eps, 1.0f - eps));
    float g = (logit + s) * 0.2f;
    return __fdividef(1.0f, 1.0f + __expf(-g));
}

__global__ void edge_gate_kernel(const int2* __restrict__ rows2,
                                 const int2* __restrict__ cols2,
                                 const int2* __restrict__ type2,
                                 const int2* __restrict__ batch2,
                                 const float2* __restrict__ eps2,
                                 float2* __restrict__ out2,
                                 int ngroups) {
    int i = blockIdx.x * blockDim.x + threadIdx.x;
    if (i >= ngroups) return;

    int2   r  = __ldcs(&rows2[i]);
    int2   c  = __ldcs(&cols2[i]);
    int2   t  = __ldcs(&type2[i]);
    int2   bb = __ldcs(&batch2[i]);
    float2 u  = __ldcs(&eps2[i]);

    float2 o;
    o.x = gate_one(r.x, c.x, t.x, bb.x, u.x);
    o.y = gate_one(r.y, c.y, t.y, bb.y, u.y);
    out2[i] = o;
}

// Scalar fallback for E not divisible by 2 (not hit for E=500000).
__global__ void edge_gate_tail_kernel(const int* __restrict__ rows,
                                      const int* __restrict__ cols,
                                      const int* __restrict__ edge_type,
                                      const int* __restrict__ batch_id,
                                      const float* __restrict__ eps_u,
                                      float* __restrict__ out,
                                      int start, int E) {
    int e = start + blockIdx.x * blockDim.x + threadIdx.x;
    if (e >= E) return;
    out[e] = gate_one(rows[e], cols[e], edge_type[e], batch_id[e], eps_u[e]);
}

extern "C" void kernel_launch(void* const* d_in, const int* in_sizes, int n_in,
                              void* d_out, int out_size) {
    const float* node_embeds = (const float*)d_in[0];  // (N, 128)
    const float* R           = (const float*)d_in[1];  // (NUM_REL, 128)
    const float* W           = (const float*)d_in[2];  // (640, 1)
    const float* b           = (const float*)d_in[3];  // (1,)
    const float* eps_u       = (const float*)d_in[4];  // (E, 1)
    const int*   edge_index  = (const int*)d_in[5];    // (2, E) int32
    const int*   edge_type   = (const int*)d_in[6];    // (E,)
    const int*   batch_id    = (const int*)d_in[7];    // (E,)
    const int*   h_index     = (const int*)d_in[8];    // (B,)
    const int*   r_index     = (const int*)d_in[9];    // (B,)
    float* out = (float*)d_out;

    const int D = 128;
    int N       = in_sizes[0] / D;
    int NUM_REL = in_sizes[1] / D;
    int E       = in_sizes[4];
    int B       = in_sizes[8];

    const float4* ne4 = (const float4*)node_embeds;
    const float4* R4  = (const float4*)R;
    const float4* W4  = (const float4*)W;

    // Pass 1: fused projections + batch dots. 2048 blocks x 8 warps.
    {
        int threads = 256;
        int blocks = 2048;
        proj_kernel<<<blocks, threads>>>(ne4, R4, W4, h_index, r_index, b,
                                         N, NUM_REL, B);
    }
    // Pass 2: edge gate, 2 edges/thread (cols slice 8B-aligned for E%2==0;
    // tail kernel covers any remainder).
    {
        int ngroups = E >> 1;
        int threads = 256;
        int blocks = (ngroups + threads - 1) / threads;
        if (blocks > 0)
            edge_gate_kernel<<<blocks, threads>>>((const int2*)edge_index,
                                                  (const int2*)(edge_index + E),
                                                  (const int2*)edge_type,
                                                  (const int2*)batch_id,
                                                  (const float2*)eps_u,
                                                  (float2*)out, ngroups);
        int tail_start = ngroups << 1;
        if (E - tail_start > 0) {
            edge_gate_tail_kernel<<<1, 256>>>(edge_index, edge_index + E,
                                              edge_type, batch_id, eps_u, out,
                                              tail_start, E);
        }
    }
}